// round 8
// baseline (speedup 1.0000x reference)
#include <cuda_runtime.h>
#include <cstdint>

// convection_vectors: (N_NODES, 3) float32      -> d_in[0]
// mesh_elements:      (E, 4)       int32        -> d_in[1]
// inv_matrices:       (E, 4, 4)    float32      -> d_in[2]
// out:                (E, 4, 3)    float32      -> d_out
//
// out[e,i,c] = sum_j inv[e,i,j] * conv[mesh[e,j], c]

#define MAX_NODES 400000

// Padded gather table: (N, 4) so each vertex is one aligned 16B load. 6.4 MB -> L2-resident.
__device__ float4 g_conv4[MAX_NODES];

__global__ void __launch_bounds__(128)
pad_conv_kernel(const float* __restrict__ conv, int n)
{
    // Allow the dependent (main) kernel to launch immediately; its
    // cudaGridDependencySynchronize() still waits for our completion
    // before it reads g_conv4.
    cudaTriggerProgrammaticLaunchCompletion();

    int i = blockIdx.x * blockDim.x + threadIdx.x;
    if (i >= n) return;
    long b = (long)i * 3;
    g_conv4[i] = make_float4(conv[b], conv[b + 1], conv[b + 2], 0.0f);
}

__device__ __forceinline__ uint32_t smem_u32(const void* p)
{
    uint32_t a;
    asm("{ .reg .u64 t; cvta.to.shared.u64 t, %1; cvt.u32.u64 %0, t; }" : "=r"(a) : "l"(p));
    return a;
}

// One thread per (element,row) unit; 2 tiles per CTA, double-buffered smem
// with pipelined TMA bulk stores (R7 winner). New in R8: PDL — the streaming
// elems/inv loads (independent of the pad table) are front-issued BEFORE
// cudaGridDependencySynchronize(), overlapping the pad kernel's execution.
__global__ void __launch_bounds__(256)
fem_row_tma2_kernel(const int4*   __restrict__ elems,
                    const float4* __restrict__ inv,
                    float*        __restrict__ out,
                    int total_rows)   // 4*E
{
    __shared__ __align__(16) float s_out[2][256 * 3];   // 2 x 3 KB tiles

    const int tile_rows = 256;

    // ---- Front-issue both tiles' independent streaming loads ----
    int tb0 = (blockIdx.x * 2 + 0) * tile_rows;
    int tb1 = (blockIdx.x * 2 + 1) * tile_rows;
    int t0 = tb0 + threadIdx.x;
    int t1 = tb1 + threadIdx.x;
    int t0c = (t0 < total_rows) ? t0 : (total_rows - 1);
    int t1c = (t1 < total_rows) ? t1 : (total_rows - 1);

    int4   iA = __ldcs(&elems[t0c >> 2]);
    int4   iB = __ldcs(&elems[t1c >> 2]);
    float4 mA = __ldcs(&inv[t0c]);
    float4 mB = __ldcs(&inv[t1c]);

    // ---- Wait for pad kernel's g_conv4 to be complete/visible ----
    cudaGridDependencySynchronize();

#pragma unroll
    for (int it = 0; it < 2; it++) {
        int tile_base = (it == 0) ? tb0 : tb1;
        int t         = (it == 0) ? t0  : t1;
        int4   idx    = (it == 0) ? iA  : iB;
        float4 m      = (it == 0) ? mA  : mB;
        bool full_tile = (tile_base + tile_rows <= total_rows);

        if (t < total_rows) {
            float4 v0 = g_conv4[idx.x];
            float4 v1 = g_conv4[idx.y];
            float4 v2 = g_conv4[idx.z];
            float4 v3 = g_conv4[idx.w];

            float r0 = fmaf(m.x, v0.x, fmaf(m.y, v1.x, fmaf(m.z, v2.x, m.w * v3.x)));
            float r1 = fmaf(m.x, v0.y, fmaf(m.y, v1.y, fmaf(m.z, v2.y, m.w * v3.y)));
            float r2 = fmaf(m.x, v0.z, fmaf(m.y, v1.z, fmaf(m.z, v2.z, m.w * v3.z)));

            if (full_tile) {
                // stride-3 word addresses: gcd(3,32)=1 -> conflict-free
                int w = threadIdx.x * 3;
                s_out[it][w + 0] = r0;
                s_out[it][w + 1] = r1;
                s_out[it][w + 2] = r2;
            } else {
                float* o = out + (long)t * 3;
                __stcs(o + 0, r0);
                __stcs(o + 1, r1);
                __stcs(o + 2, r2);
            }
        }

        if (full_tile) {
            asm volatile("fence.proxy.async.shared::cta;" ::: "memory");
            __syncthreads();
            if (threadIdx.x == 0) {
                uint32_t saddr = smem_u32(s_out[it]);
                float* gptr = out + (long)tile_base * 3;   // 3072B-aligned chunk
                asm volatile(
                    "cp.async.bulk.global.shared::cta.bulk_group [%0], [%1], %2;"
                    :: "l"(gptr), "r"(saddr), "r"(tile_rows * 3 * 4) : "memory");
                asm volatile("cp.async.bulk.commit_group;" ::: "memory");
            }
        }
    }

    // Single drain at CTA end (covers both buffers).
    if (threadIdx.x == 0)
        asm volatile("cp.async.bulk.wait_group 0;" ::: "memory");
}

extern "C" void kernel_launch(void* const* d_in, const int* in_sizes, int n_in,
                              void* d_out, int out_size)
{
    const float* conv  = (const float*)d_in[0];
    const int4*  elems = (const int4*)d_in[1];
    const float4* inv  = (const float4*)d_in[2];
    float* out = (float*)d_out;

    int n_nodes = in_sizes[0] / 3;
    int E = in_sizes[1] / 4;
    int total_rows = 4 * E;

    pad_conv_kernel<<<(n_nodes + 127) / 128, 128>>>(conv, n_nodes);

    int rows_per_cta = 512;   // 2 tiles x 256
    int grid = (total_rows + rows_per_cta - 1) / rows_per_cta;

    // Launch main kernel with Programmatic Dependent Launch so it can begin
    // (and run its independent streaming loads) while pad_conv_kernel drains.
    cudaLaunchConfig_t cfg = {};
    cfg.gridDim  = dim3(grid, 1, 1);
    cfg.blockDim = dim3(256, 1, 1);
    cfg.dynamicSmemBytes = 0;
    cudaLaunchAttribute attrs[1];
    attrs[0].id = cudaLaunchAttributeProgrammaticStreamSerialization;
    attrs[0].val.programmaticStreamSerializationAllowed = 1;
    cfg.attrs = attrs;
    cfg.numAttrs = 1;

    cudaLaunchKernelEx(&cfg, fem_row_tma2_kernel, elems, inv, out, total_rows);
}

// round 9
// speedup vs baseline: 1.0684x; 1.0684x over previous
#include <cuda_runtime.h>
#include <cstdint>

// convection_vectors: (N_NODES, 3) float32      -> d_in[0]
// mesh_elements:      (E, 4)       int32        -> d_in[1]
// inv_matrices:       (E, 4, 4)    float32      -> d_in[2]
// out:                (E, 4, 3)    float32      -> d_out
//
// out[e,i,c] = sum_j inv[e,i,j] * conv[mesh[e,j], c]

#define MAX_NODES 400000

// Padded gather table: (N, 4) so each vertex is one aligned 16B load. 6.4 MB -> L2-resident.
__device__ float4 g_conv4[MAX_NODES];

__global__ void __launch_bounds__(128)
pad_conv_kernel(const float* __restrict__ conv, int n)
{
    int i = blockIdx.x * blockDim.x + threadIdx.x;
    if (i >= n) return;
    long b = (long)i * 3;
    g_conv4[i] = make_float4(conv[b], conv[b + 1], conv[b + 2], 0.0f);
}

__device__ __forceinline__ uint32_t smem_u32(const void* p)
{
    uint32_t a;
    asm("{ .reg .u64 t; cvta.to.shared.u64 t, %1; cvt.u32.u64 %0, t; }" : "=r"(a) : "l"(p));
    return a;
}

// One thread per (element,row) unit; each CTA processes FOUR consecutive
// 256-row tiles, each staged into its own smem buffer (conflict-free stride-3
// STS) and written out with a pipelined 1D TMA bulk store. Single drain at
// CTA end -> up to 4 outstanding bulk groups overlap later tiles' compute.
__global__ void __launch_bounds__(256)
fem_row_tma4_kernel(const int4*   __restrict__ elems,
                    const float4* __restrict__ inv,
                    float*        __restrict__ out,
                    int total_rows)   // 4*E
{
    __shared__ __align__(16) float s_out[4][256 * 3];   // 4 x 3 KB tiles

    const int tile_rows = 256;

#pragma unroll
    for (int it = 0; it < 4; it++) {
        int tile_base = (blockIdx.x * 4 + it) * tile_rows;
        if (tile_base >= total_rows) break;

        int t = tile_base + threadIdx.x;
        bool full_tile = (tile_base + tile_rows <= total_rows);

        if (t < total_rows) {
            int4 idx = __ldcs(&elems[t >> 2]);
            float4 m = __ldcs(&inv[t]);

            float4 v0 = g_conv4[idx.x];
            float4 v1 = g_conv4[idx.y];
            float4 v2 = g_conv4[idx.z];
            float4 v3 = g_conv4[idx.w];

            float r0 = fmaf(m.x, v0.x, fmaf(m.y, v1.x, fmaf(m.z, v2.x, m.w * v3.x)));
            float r1 = fmaf(m.x, v0.y, fmaf(m.y, v1.y, fmaf(m.z, v2.y, m.w * v3.y)));
            float r2 = fmaf(m.x, v0.z, fmaf(m.y, v1.z, fmaf(m.z, v2.z, m.w * v3.z)));

            if (full_tile) {
                // stride-3 word addresses: gcd(3,32)=1 -> conflict-free
                int w = threadIdx.x * 3;
                s_out[it][w + 0] = r0;
                s_out[it][w + 1] = r1;
                s_out[it][w + 2] = r2;
            } else {
                float* o = out + (long)t * 3;
                __stcs(o + 0, r0);
                __stcs(o + 1, r1);
                __stcs(o + 2, r2);
            }
        }

        if (full_tile) {
            asm volatile("fence.proxy.async.shared::cta;" ::: "memory");
            __syncthreads();
            if (threadIdx.x == 0) {
                uint32_t saddr = smem_u32(s_out[it]);
                float* gptr = out + (long)tile_base * 3;   // 3072B-aligned chunk
                asm volatile(
                    "cp.async.bulk.global.shared::cta.bulk_group [%0], [%1], %2;"
                    :: "l"(gptr), "r"(saddr), "r"(tile_rows * 3 * 4) : "memory");
                asm volatile("cp.async.bulk.commit_group;" ::: "memory");
            }
        }
    }

    // Single drain at CTA end (covers all buffers).
    if (threadIdx.x == 0)
        asm volatile("cp.async.bulk.wait_group 0;" ::: "memory");
}

extern "C" void kernel_launch(void* const* d_in, const int* in_sizes, int n_in,
                              void* d_out, int out_size)
{
    const float* conv  = (const float*)d_in[0];
    const int4*  elems = (const int4*)d_in[1];
    const float4* inv  = (const float4*)d_in[2];
    float* out = (float*)d_out;

    int n_nodes = in_sizes[0] / 3;
    int E = in_sizes[1] / 4;
    int total_rows = 4 * E;

    pad_conv_kernel<<<(n_nodes + 127) / 128, 128>>>(conv, n_nodes);

    int rows_per_cta = 1024;   // 4 tiles x 256
    int grid = (total_rows + rows_per_cta - 1) / rows_per_cta;
    fem_row_tma4_kernel<<<grid, 256>>>(elems, inv, out, total_rows);
}

// round 10
// speedup vs baseline: 1.0947x; 1.0246x over previous
#include <cuda_runtime.h>
#include <cstdint>

// convection_vectors: (N_NODES, 3) float32      -> d_in[0]
// mesh_elements:      (E, 4)       int32        -> d_in[1]
// inv_matrices:       (E, 4, 4)    float32      -> d_in[2]
// out:                (E, 4, 3)    float32      -> d_out
//
// out[e,i,c] = sum_j inv[e,i,j] * conv[mesh[e,j], c]

#define MAX_NODES 400000

// Padded gather table: (N, 4) so each vertex is one aligned 16B load. 6.4 MB -> L2-resident.
__device__ float4 g_conv4[MAX_NODES];

// Vectorized pad: one thread per 4 nodes. Reads 3 contiguous float4 (48B,
// fully coalesced), writes 4 float4. 28 wavefronts per 128 nodes vs 52 for
// the thread-per-node version.
__global__ void __launch_bounds__(256)
pad_conv4_kernel(const float4* __restrict__ conv4, int n_nodes)
{
    int j = blockIdx.x * blockDim.x + threadIdx.x;   // group of 4 nodes
    int base = j * 4;
    if (base >= n_nodes) return;

    if (base + 4 <= n_nodes) {
        float4 c0 = __ldg(&conv4[j * 3 + 0]);
        float4 c1 = __ldg(&conv4[j * 3 + 1]);
        float4 c2 = __ldg(&conv4[j * 3 + 2]);
        g_conv4[base + 0] = make_float4(c0.x, c0.y, c0.z, 0.0f);
        g_conv4[base + 1] = make_float4(c0.w, c1.x, c1.y, 0.0f);
        g_conv4[base + 2] = make_float4(c1.z, c1.w, c2.x, 0.0f);
        g_conv4[base + 3] = make_float4(c2.y, c2.z, c2.w, 0.0f);
    } else {
        const float* conv = (const float*)conv4;
        for (int i = base; i < n_nodes; i++) {
            long b = (long)i * 3;
            g_conv4[i] = make_float4(conv[b], conv[b + 1], conv[b + 2], 0.0f);
        }
    }
}

__device__ __forceinline__ uint32_t smem_u32(const void* p)
{
    uint32_t a;
    asm("{ .reg .u64 t; cvta.to.shared.u64 t, %1; cvt.u32.u64 %0, t; }" : "=r"(a) : "l"(p));
    return a;
}

// R7 winner, unchanged: one thread per (element,row) unit; each CTA processes
// TWO consecutive 256-row tiles, double-buffered smem (conflict-free stride-3
// STS) + pipelined 1D TMA bulk stores; single drain at CTA end.
__global__ void __launch_bounds__(256)
fem_row_tma2_kernel(const int4*   __restrict__ elems,
                    const float4* __restrict__ inv,
                    float*        __restrict__ out,
                    int total_rows)   // 4*E
{
    __shared__ __align__(16) float s_out[2][256 * 3];   // 2 x 3 KB tiles

    const int tile_rows = 256;

#pragma unroll
    for (int it = 0; it < 2; it++) {
        int tile_base = (blockIdx.x * 2 + it) * tile_rows;
        int t = tile_base + threadIdx.x;
        bool full_tile = (tile_base + tile_rows <= total_rows);

        if (t < total_rows) {
            int4 idx = __ldcs(&elems[t >> 2]);
            float4 m = __ldcs(&inv[t]);

            float4 v0 = g_conv4[idx.x];
            float4 v1 = g_conv4[idx.y];
            float4 v2 = g_conv4[idx.z];
            float4 v3 = g_conv4[idx.w];

            float r0 = fmaf(m.x, v0.x, fmaf(m.y, v1.x, fmaf(m.z, v2.x, m.w * v3.x)));
            float r1 = fmaf(m.x, v0.y, fmaf(m.y, v1.y, fmaf(m.z, v2.y, m.w * v3.y)));
            float r2 = fmaf(m.x, v0.z, fmaf(m.y, v1.z, fmaf(m.z, v2.z, m.w * v3.z)));

            if (full_tile) {
                // stride-3 word addresses: gcd(3,32)=1 -> conflict-free
                int w = threadIdx.x * 3;
                s_out[it][w + 0] = r0;
                s_out[it][w + 1] = r1;
                s_out[it][w + 2] = r2;
            } else {
                float* o = out + (long)t * 3;
                __stcs(o + 0, r0);
                __stcs(o + 1, r1);
                __stcs(o + 2, r2);
            }
        }

        if (full_tile) {
            asm volatile("fence.proxy.async.shared::cta;" ::: "memory");
            __syncthreads();
            if (threadIdx.x == 0) {
                uint32_t saddr = smem_u32(s_out[it]);
                float* gptr = out + (long)tile_base * 3;   // 3072B-aligned chunk
                asm volatile(
                    "cp.async.bulk.global.shared::cta.bulk_group [%0], [%1], %2;"
                    :: "l"(gptr), "r"(saddr), "r"(tile_rows * 3 * 4) : "memory");
                asm volatile("cp.async.bulk.commit_group;" ::: "memory");
            }
        }
    }

    // Single drain at CTA end (covers both buffers).
    if (threadIdx.x == 0)
        asm volatile("cp.async.bulk.wait_group 0;" ::: "memory");
}

extern "C" void kernel_launch(void* const* d_in, const int* in_sizes, int n_in,
                              void* d_out, int out_size)
{
    const float* conv  = (const float*)d_in[0];
    const int4*  elems = (const int4*)d_in[1];
    const float4* inv  = (const float4*)d_in[2];
    float* out = (float*)d_out;

    int n_nodes = in_sizes[0] / 3;
    int E = in_sizes[1] / 4;
    int total_rows = 4 * E;

    int n_groups = (n_nodes + 3) / 4;
    pad_conv4_kernel<<<(n_groups + 255) / 256, 256>>>((const float4*)conv, n_nodes);

    int rows_per_cta = 512;   // 2 tiles x 256
    int grid = (total_rows + rows_per_cta - 1) / rows_per_cta;
    fem_row_tma2_kernel<<<grid, 256>>>(elems, inv, out, total_rows);
}